// round 11
// baseline (speedup 1.0000x reference)
#include <cuda_runtime.h>
#include <cuda_fp16.h>
#include <math.h>
#include <stdint.h>

#define Dk     128
#define NROWS  8192
#define BM     128
#define BN     64

// smem byte offsets
#define SM_A     0
#define SM_B     (32*1024)
#define SM_SQA   (48*1024)
#define SM_SQB   (SM_SQA + 512)
#define SM_TOTAL (SM_SQB + 256)   // 49408 B -> 3 CTAs/SM (smem-wise)

__device__ float   g_sq[NROWS];
__device__ __half  g_h[NROWS * Dk];

__device__ __forceinline__ uint32_t smem_u32(const void* p) {
    uint32_t a;
    asm("{ .reg .u64 t; cvta.to.shared.u64 t, %1; cvt.u32.u64 %0, t; }" : "=r"(a) : "l"(p));
    return a;
}

#define CP_ASYNC16(smaddr, gptr) \
    asm volatile("cp.async.ca.shared.global [%0], [%1], 16;" \
                 :: "r"(smaddr), "l"(gptr) : "memory")
#define CP_ASYNC_WAIT() do { \
    asm volatile("cp.async.commit_group;" ::: "memory"); \
    asm volatile("cp.async.wait_group 0;" ::: "memory"); \
} while (0)

#define LDSM_X4(r0, r1, r2, r3, addr) \
    asm volatile("ldmatrix.sync.aligned.m8n8.x4.shared.b16 {%0,%1,%2,%3}, [%4];" \
                 : "=r"(r0), "=r"(r1), "=r"(r2), "=r"(r3) : "r"(addr))

#define MMA16816F16(d, a0, a1, a2, a3, b0, b1) \
    asm volatile("mma.sync.aligned.m16n8k16.row.col.f32.f16.f16.f32 " \
                 "{%0,%1,%2,%3}, {%4,%5,%6,%7}, {%8,%9}, {%0,%1,%2,%3};" \
                 : "+f"((d)[0]), "+f"((d)[1]), "+f"((d)[2]), "+f"((d)[3]) \
                 : "r"(a0), "r"(a1), "r"(a2), "r"(a3), "r"(b0), "r"(b1))

// ---------------- fused precompute: fp16 convert + row squared-norms ----------------
__global__ void prep_kernel(const float* __restrict__ f) {
    const int wid = threadIdx.x >> 5;
    const int l   = threadIdx.x & 31;
    const int row = blockIdx.x * 8 + wid;
    const float4 v = *(const float4*)(f + (size_t)row * Dk + l * 4);
    float x[4] = {v.x, v.y, v.z, v.w};
    __half h[4];
    float s = 0.f;
#pragma unroll
    for (int k = 0; k < 4; k++) {
        h[k] = __float2half_rn(x[k]);
        s = fmaf(x[k], x[k], s);
    }
    *(uint2*)&g_h[(size_t)row * Dk + l * 4] = *(uint2*)h;
#pragma unroll
    for (int d = 16; d > 0; d >>= 1)
        s += __shfl_xor_sync(0xFFFFFFFFu, s, d);
    if (l == 0) g_sq[row] = s;
}

// ---------------- main kernel ----------------
// Tiles (I,J): rows [I*128, ...), cols [J*64, ...), J >= 2I. 4160 CTAs.
// dot = fp16(A) * fp16(B)^T, f32 accum. out = -sqrt(max(sqi+sqj-2dot,0)).
// Crossing tiles (J in {2I, 2I+1}) predicate element ownership.
__global__ __launch_bounds__(256, 3)
void dist_kernel(float* __restrict__ out, int N) {
    extern __shared__ __align__(1024) char smem[];
    const uint32_t sb = smem_u32(smem);

    // ---- tile indices from linear id: off(I) = I*(129-I), integer search ----
    const int idx = blockIdx.x;
    int I = 0;
    while (I < 63 && (I + 1) * (128 - I) <= idx) I++;
    const int J = 2 * I + (idx - I * (129 - I));
    const int bm = I * BM;
    const int bn = J * BN;
    const bool crossing = (J - 2 * I) < 2;

    const int tid = threadIdx.x;
    const int wid = tid >> 5;
    const int l   = tid & 31;

    // ---- cp.async operand tiles: row = 16 x 16B chunks, swizzle c ^= (r&7) ----
    const uint4* h = (const uint4*)g_h;
#pragma unroll
    for (int it = 0; it < 8; it++) {            // A: 128 rows x 16 chunks
        int u = it * 256 + tid;
        int r = u >> 4, c = u & 15;
        uint32_t off = r * 256 + ((c ^ (r & 7)) << 4);
        CP_ASYNC16(sb + SM_A + off, h + (size_t)(bm + r) * 16 + c);
    }
#pragma unroll
    for (int it = 0; it < 4; it++) {            // B: 64 rows x 16 chunks
        int u = it * 256 + tid;
        int r = u >> 4, c = u & 15;
        uint32_t off = r * 256 + ((c ^ (r & 7)) << 4);
        CP_ASYNC16(sb + SM_B + off, h + (size_t)(bn + r) * 16 + c);
    }
    if (tid < 128) ((float*)(smem + SM_SQA))[tid] = g_sq[bm + tid];
    else if (tid < 192) ((float*)(smem + SM_SQB))[tid - 128] = g_sq[bn + tid - 128];
    CP_ASYNC_WAIT();
    __syncthreads();

    // ---- warp tiling: 4(m) x 2(n) warps, each 32(m) x 32(n) ----
    const int wm = (wid & 3) * 32;
    const int wn = (wid >> 2) * 32;

    uint32_t pA[2], sA[2];
#pragma unroll
    for (int mt = 0; mt < 2; mt++) {
        int r = wm + mt * 16 + (l & 15);
        pA[mt] = r * 256;
        sA[mt] = (r & 7) << 4;
    }
    const int hA = l >> 4;

    uint32_t pB[2], sB[2];
    {
        int g = l >> 3;
        int rb = ((g >> 1) << 3) + (l & 7);
#pragma unroll
        for (int nt = 0; nt < 2; nt++) {
            int r = wn + nt * 16 + rb;
            pB[nt] = r * 256;
            sB[nt] = (r & 7) << 4;
        }
    }
    const int hB = (l >> 3) & 1;

    float acc[2][4][4];
#pragma unroll
    for (int mt = 0; mt < 2; mt++)
#pragma unroll
        for (int nt = 0; nt < 4; nt++)
#pragma unroll
            for (int q = 0; q < 4; q++) acc[mt][nt][q] = 0.f;

    // ---- mainloop: 8 k-steps of 16, single fp16 term ----
#pragma unroll
    for (int ks = 0; ks < 8; ks++) {
        const uint32_t cA = (uint32_t)((ks * 2 + hA) << 4);
        const uint32_t cB = (uint32_t)((ks * 2 + hB) << 4);
        uint32_t a[2][4], b[2][4];
#pragma unroll
        for (int mt = 0; mt < 2; mt++) {
            uint32_t o = pA[mt] + (cA ^ sA[mt]);
            LDSM_X4(a[mt][0], a[mt][1], a[mt][2], a[mt][3], sb + SM_A + o);
        }
#pragma unroll
        for (int nt = 0; nt < 2; nt++) {
            uint32_t o = pB[nt] + (cB ^ sB[nt]);
            LDSM_X4(b[nt][0], b[nt][1], b[nt][2], b[nt][3], sb + SM_B + o);
        }
#pragma unroll
        for (int mt = 0; mt < 2; mt++) {
#pragma unroll
            for (int n8 = 0; n8 < 4; n8++) {
                int n4 = n8 >> 1, nh = (n8 & 1) * 2;
                MMA16816F16(acc[mt][n8], a[mt][0], a[mt][1], a[mt][2], a[mt][3],
                            b[n4][nh], b[n4][nh + 1]);
            }
        }
    }

    // ---- epilogue (register path, streaming stores) ----
    const int lr = l >> 2;            // 0..7
    const int lc = (l & 3) * 2;       // 0,2,4,6
    float sqa[2][2], sqb[4][2];
#pragma unroll
    for (int mt = 0; mt < 2; mt++) {
        sqa[mt][0] = ((const float*)(smem + SM_SQA))[wm + mt * 16 + lr];
        sqa[mt][1] = ((const float*)(smem + SM_SQA))[wm + mt * 16 + lr + 8];
    }
#pragma unroll
    for (int nt = 0; nt < 4; nt++) {
        sqb[nt][0] = ((const float*)(smem + SM_SQB))[wn + nt * 8 + lc];
        sqb[nt][1] = ((const float*)(smem + SM_SQB))[wn + nt * 8 + lc + 1];
    }

#pragma unroll
    for (int mt = 0; mt < 2; mt++) {
        const int row0 = bm + wm + mt * 16 + lr;
        const int row1 = row0 + 8;
#pragma unroll
        for (int nt = 0; nt < 4; nt++) {
            const int col = bn + wn + nt * 8 + lc;
            float v00 = -sqrtf(fmaxf(fmaf(-2.f, acc[mt][nt][0], sqa[mt][0] + sqb[nt][0]), 0.f));
            float v01 = -sqrtf(fmaxf(fmaf(-2.f, acc[mt][nt][1], sqa[mt][0] + sqb[nt][1]), 0.f));
            float v10 = -sqrtf(fmaxf(fmaf(-2.f, acc[mt][nt][2], sqa[mt][1] + sqb[nt][0]), 0.f));
            float v11 = -sqrtf(fmaxf(fmaf(-2.f, acc[mt][nt][3], sqa[mt][1] + sqb[nt][1]), 0.f));
            if (!crossing) {
                __stcs((float2*)&out[(size_t)row0 * N + col], make_float2(v00, v01));
                __stcs((float2*)&out[(size_t)row1 * N + col], make_float2(v10, v11));
                __stcs(&out[(size_t)col * N + row0],       v00);
                __stcs(&out[(size_t)col * N + row1],       v10);
                __stcs(&out[(size_t)(col + 1) * N + row0], v01);
                __stcs(&out[(size_t)(col + 1) * N + row1], v11);
            } else {
                // element-wise ownership: col>row -> both; col==row -> 0; col<row -> skip
                if (col > row0) {
                    __stcs(&out[(size_t)row0 * N + col], v00);
                    __stcs(&out[(size_t)col * N + row0], v00);
                } else if (col == row0) __stcs(&out[(size_t)row0 * N + col], 0.f);
                if (col + 1 > row0) {
                    __stcs(&out[(size_t)row0 * N + col + 1], v01);
                    __stcs(&out[(size_t)(col + 1) * N + row0], v01);
                } else if (col + 1 == row0) __stcs(&out[(size_t)row0 * N + col + 1], 0.f);
                if (col > row1) {
                    __stcs(&out[(size_t)row1 * N + col], v10);
                    __stcs(&out[(size_t)col * N + row1], v10);
                } else if (col == row1) __stcs(&out[(size_t)row1 * N + col], 0.f);
                if (col + 1 > row1) {
                    __stcs(&out[(size_t)row1 * N + col + 1], v11);
                    __stcs(&out[(size_t)(col + 1) * N + row1], v11);
                } else if (col + 1 == row1) __stcs(&out[(size_t)row1 * N + col + 1], 0.f);
            }
        }
    }
}

// ---------------- launch ----------------
extern "C" void kernel_launch(void* const* d_in, const int* in_sizes, int n_in,
                              void* d_out, int out_size) {
    const float* f   = (const float*)d_in[0];
    float*       out = (float*)d_out;
    const int N = in_sizes[0] / Dk;        // 8192

    prep_kernel<<<N / 8, 256>>>(f);

    cudaFuncSetAttribute(dist_kernel,
                         cudaFuncAttributeMaxDynamicSharedMemorySize, SM_TOTAL);
    const int ntiles = 4160;               // sum_{I=0}^{63} (128 - 2I)
    dist_kernel<<<ntiles, 256, SM_TOTAL>>>(out, N);
}

// round 13
// speedup vs baseline: 1.7268x; 1.7268x over previous
#include <cuda_runtime.h>
#include <cuda_fp16.h>
#include <math.h>
#include <stdint.h>

#define Dk     128
#define NROWS  8192
#define BT     128          // square tile

// smem byte offsets
#define SM_A     0
#define SM_B     (32*1024)
#define SM_SQA   (64*1024)
#define SM_SQB   (SM_SQA + 512)
#define SM_TOTAL (SM_SQB + 512)   // 66560 B -> 2 CTAs/SM

__device__ float   g_sq[NROWS];
__device__ __half  g_h[NROWS * Dk];

__device__ __forceinline__ uint32_t smem_u32(const void* p) {
    uint32_t a;
    asm("{ .reg .u64 t; cvta.to.shared.u64 t, %1; cvt.u32.u64 %0, t; }" : "=r"(a) : "l"(p));
    return a;
}

#define CP_ASYNC16(smaddr, gptr) \
    asm volatile("cp.async.ca.shared.global [%0], [%1], 16;" \
                 :: "r"(smaddr), "l"(gptr) : "memory")
#define CP_ASYNC_WAIT() do { \
    asm volatile("cp.async.commit_group;" ::: "memory"); \
    asm volatile("cp.async.wait_group 0;" ::: "memory"); \
} while (0)

#define LDSM_X4(r0, r1, r2, r3, addr) \
    asm volatile("ldmatrix.sync.aligned.m8n8.x4.shared.b16 {%0,%1,%2,%3}, [%4];" \
                 : "=r"(r0), "=r"(r1), "=r"(r2), "=r"(r3) : "r"(addr))

#define MMA16816F16(d, a0, a1, a2, a3, b0, b1) \
    asm volatile("mma.sync.aligned.m16n8k16.row.col.f32.f16.f16.f32 " \
                 "{%0,%1,%2,%3}, {%4,%5,%6,%7}, {%8,%9}, {%0,%1,%2,%3};" \
                 : "+f"((d)[0]), "+f"((d)[1]), "+f"((d)[2]), "+f"((d)[3]) \
                 : "r"(a0), "r"(a1), "r"(a2), "r"(a3), "r"(b0), "r"(b1))

// ---------------- fused precompute: fp16 convert + row squared-norms ----------------
__global__ void prep_kernel(const float* __restrict__ f) {
    const int wid = threadIdx.x >> 5;
    const int l   = threadIdx.x & 31;
    const int row = blockIdx.x * 8 + wid;
    const float4 v = *(const float4*)(f + (size_t)row * Dk + l * 4);
    float x[4] = {v.x, v.y, v.z, v.w};
    __half h[4];
    float s = 0.f;
#pragma unroll
    for (int k = 0; k < 4; k++) {
        h[k] = __float2half_rn(x[k]);
        s = fmaf(x[k], x[k], s);
    }
    *(uint2*)&g_h[(size_t)row * Dk + l * 4] = *(uint2*)h;
#pragma unroll
    for (int d = 16; d > 0; d >>= 1)
        s += __shfl_xor_sync(0xFFFFFFFFu, s, d);
    if (l == 0) g_sq[row] = s;
}

// ---------------- main kernel ----------------
// Upper-triangle square tiles (I<=J): 2080 CTAs. dot = fp16(A)*fp16(B)^T, f32 accum.
// out = -sqrt(max(sqi+sqj-2dot,0)); off-diag tiles stored to (I,J) and (J,I).
__global__ __launch_bounds__(256, 2)
void dist_kernel(float* __restrict__ out, int N) {
    extern __shared__ __align__(1024) char smem[];
    const uint32_t sb = smem_u32(smem);

    // ---- tile indices (I <= J) ----
    const int idx = blockIdx.x;
    int J = (int)((sqrtf(8.f * idx + 1.f) - 1.f) * 0.5f);
    while ((J + 1) * (J + 2) / 2 <= idx) J++;
    while (J * (J + 1) / 2 > idx) J--;
    const int I = idx - J * (J + 1) / 2;
    const int bm = I * BT;
    const int bn = J * BT;
    const bool diag = (I == J);

    const int tid = threadIdx.x;
    const int wid = tid >> 5;
    const int l   = tid & 31;

    // ---- cp.async operand tiles: row = 16 x 16B chunks, swizzle c ^= (r&7) ----
    const uint4* h = (const uint4*)g_h;
#pragma unroll
    for (int it = 0; it < 8; it++) {
        int u = it * 256 + tid;            // 0..2047
        int r = u >> 4, c = u & 15;
        uint32_t off = r * 256 + ((c ^ (r & 7)) << 4);
        CP_ASYNC16(sb + SM_A + off, h + (size_t)(bm + r) * 16 + c);
        CP_ASYNC16(sb + SM_B + off, h + (size_t)(bn + r) * 16 + c);
    }
    if (tid < 128) ((float*)(smem + SM_SQA))[tid] = g_sq[bm + tid];
    else ((float*)(smem + SM_SQB))[tid - 128] = g_sq[bn + tid - 128];
    CP_ASYNC_WAIT();
    __syncthreads();

    // ---- warp tiling: 4(m) x 2(n) warps, each 32(m) x 64(n) ----
    const int wm = (wid & 3) * 32;
    const int wn = (wid >> 2) * 64;

    uint32_t pA[2], sA[2];
#pragma unroll
    for (int mt = 0; mt < 2; mt++) {
        int r = wm + mt * 16 + (l & 15);
        pA[mt] = r * 256;
        sA[mt] = (r & 7) << 4;
    }
    const int hA = l >> 4;

    uint32_t pB[4], sB[4];
    {
        int g = l >> 3;
        int rb = ((g >> 1) << 3) + (l & 7);
#pragma unroll
        for (int nt = 0; nt < 4; nt++) {
            int r = wn + nt * 16 + rb;
            pB[nt] = r * 256;
            sB[nt] = (r & 7) << 4;
        }
    }
    const int hB = (l >> 3) & 1;

    float acc[2][8][4];
#pragma unroll
    for (int mt = 0; mt < 2; mt++)
#pragma unroll
        for (int nt = 0; nt < 8; nt++)
#pragma unroll
            for (int q = 0; q < 4; q++) acc[mt][nt][q] = 0.f;

    // ---- mainloop: 8 k-steps of 16, single fp16 term ----
#pragma unroll
    for (int ks = 0; ks < 8; ks++) {
        const uint32_t cA = (uint32_t)((ks * 2 + hA) << 4);
        const uint32_t cB = (uint32_t)((ks * 2 + hB) << 4);
        uint32_t a[2][4];
#pragma unroll
        for (int mt = 0; mt < 2; mt++) {
            uint32_t o = pA[mt] + (cA ^ sA[mt]);
            LDSM_X4(a[mt][0], a[mt][1], a[mt][2], a[mt][3], sb + SM_A + o);
        }
#pragma unroll
        for (int n4 = 0; n4 < 4; n4++) {
            uint32_t o = pB[n4] + (cB ^ sB[n4]);
            uint32_t b[4];
            LDSM_X4(b[0], b[1], b[2], b[3], sb + SM_B + o);
#pragma unroll
            for (int mt = 0; mt < 2; mt++) {
#pragma unroll
                for (int nh = 0; nh < 2; nh++) {
                    MMA16816F16(acc[mt][n4 * 2 + nh], a[mt][0], a[mt][1], a[mt][2], a[mt][3],
                                b[nh * 2], b[nh * 2 + 1]);
                }
            }
        }
    }

    // ---- epilogue (register path, streaming stores) ----
    const int lr = l >> 2;            // 0..7
    const int lc = (l & 3) * 2;       // 0,2,4,6
    float sqa[2][2], sqb[8][2];
#pragma unroll
    for (int mt = 0; mt < 2; mt++) {
        sqa[mt][0] = ((const float*)(smem + SM_SQA))[wm + mt * 16 + lr];
        sqa[mt][1] = ((const float*)(smem + SM_SQA))[wm + mt * 16 + lr + 8];
    }
#pragma unroll
    for (int nt = 0; nt < 8; nt++) {
        sqb[nt][0] = ((const float*)(smem + SM_SQB))[wn + nt * 8 + lc];
        sqb[nt][1] = ((const float*)(smem + SM_SQB))[wn + nt * 8 + lc + 1];
    }

#pragma unroll
    for (int mt = 0; mt < 2; mt++) {
        const int row0 = bm + wm + mt * 16 + lr;
        const int row1 = row0 + 8;
        float* __restrict__ pr0 = out + (size_t)row0 * N + bn;
        float* __restrict__ pr1 = out + (size_t)row1 * N + bn;
#pragma unroll
        for (int nt = 0; nt < 8; nt++) {
            const int c  = wn + nt * 8 + lc;      // local col
            const int col = bn + c;
            float v00 = -sqrtf(fmaxf(fmaf(-2.f, acc[mt][nt][0], sqa[mt][0] + sqb[nt][0]), 0.f));
            float v01 = -sqrtf(fmaxf(fmaf(-2.f, acc[mt][nt][1], sqa[mt][0] + sqb[nt][1]), 0.f));
            float v10 = -sqrtf(fmaxf(fmaf(-2.f, acc[mt][nt][2], sqa[mt][1] + sqb[nt][0]), 0.f));
            float v11 = -sqrtf(fmaxf(fmaf(-2.f, acc[mt][nt][3], sqa[mt][1] + sqb[nt][1]), 0.f));
            if (!diag) {
                __stcs((float2*)(pr0 + c), make_float2(v00, v01));
                __stcs((float2*)(pr1 + c), make_float2(v10, v11));
                __stcs(&out[(size_t)col * N + row0],       v00);
                __stcs(&out[(size_t)col * N + row1],       v10);
                __stcs(&out[(size_t)(col + 1) * N + row0], v01);
                __stcs(&out[(size_t)(col + 1) * N + row1], v11);
            } else {
                // element-wise ownership: col>row -> both; col==row -> 0; col<row -> skip
                if (col > row0) {
                    __stcs(pr0 + c, v00);
                    __stcs(&out[(size_t)col * N + row0], v00);
                } else if (col == row0) __stcs(pr0 + c, 0.f);
                if (col + 1 > row0) {
                    __stcs(pr0 + c + 1, v01);
                    __stcs(&out[(size_t)(col + 1) * N + row0], v01);
                } else if (col + 1 == row0) __stcs(pr0 + c + 1, 0.f);
                if (col > row1) {
                    __stcs(pr1 + c, v10);
                    __stcs(&out[(size_t)col * N + row1], v10);
                } else if (col == row1) __stcs(pr1 + c, 0.f);
                if (col + 1 > row1) {
                    __stcs(pr1 + c + 1, v11);
                    __stcs(&out[(size_t)(col + 1) * N + row1], v11);
                } else if (col + 1 == row1) __stcs(pr1 + c + 1, 0.f);
            }
        }
    }
}

// ---------------- launch ----------------
extern "C" void kernel_launch(void* const* d_in, const int* in_sizes, int n_in,
                              void* d_out, int out_size) {
    const float* f   = (const float*)d_in[0];
    float*       out = (float*)d_out;
    const int N = in_sizes[0] / Dk;        // 8192
    const int T = N / BT;                  // 64
    const int ntiles = T * (T + 1) / 2;    // 2080

    prep_kernel<<<N / 8, 256>>>(f);

    cudaFuncSetAttribute(dist_kernel,
                         cudaFuncAttributeMaxDynamicSharedMemorySize, SM_TOTAL);
    dist_kernel<<<ntiles, 256, SM_TOTAL>>>(out, N);
}